// round 16
// baseline (speedup 1.0000x reference)
#include <cuda_runtime.h>
#include <cstdint>

#define N_NODES 30000
#define M_NB    16
#define NFEAT_  1024
#define NCLS    16
#define KCAPS   8
#define DDIM    32
#define DIM     256

// Scratch buffers (no allocation allowed -> device globals)
__device__ float g_h0[(size_t)N_NODES * DIM];
__device__ float g_xa[(size_t)N_NODES * DIM];
__device__ float g_xb[(size_t)N_NODES * DIM];

// ---------------------------------------------------------------------------
// Kernel 1: h0 = relu(x @ pca_w + pca_b)   [30000,1024]x[1024,256]
// Classic 128x128x8 double-buffered SGEMM, 256 threads, 8x8 microtile.
// ---------------------------------------------------------------------------
#define BM 128
#define BN 128
#define BK 8

__global__ __launch_bounds__(256, 2)
void gemm_pca_kernel(const float* __restrict__ X,
                     const float* __restrict__ W,
                     const float* __restrict__ Bias)
{
    __shared__ __align__(16) float As[2][BK][BM];
    __shared__ __align__(16) float Bs[2][BK][BN];

    const int t  = threadIdx.x;
    const int m0 = blockIdx.x * BM;
    const int n0 = blockIdx.y * BN;

    // A-tile load mapping: 1 float4 per thread
    const int ar = t >> 1;          // 0..127 (row within tile)
    const int ac = (t & 1) * 4;     // 0 or 4 (col within BK)
    // B-tile load mapping: 1 float4 per thread
    const int br = t >> 5;          // 0..7
    const int bc = (t & 31) * 4;    // 0..124

    const int tx = t & 15;
    const int ty = t >> 4;

    float acc[8][8];
#pragma unroll
    for (int i = 0; i < 8; ++i)
#pragma unroll
        for (int j = 0; j < 8; ++j) acc[i][j] = 0.f;

    // preload tile 0
    {
        const int gm = m0 + ar;
        float4 a = make_float4(0.f, 0.f, 0.f, 0.f);
        if (gm < N_NODES) a = *(const float4*)(X + (size_t)gm * NFEAT_ + ac);
        float4 b = *(const float4*)(W + (size_t)br * DIM + n0 + bc);
        As[0][ac + 0][ar] = a.x; As[0][ac + 1][ar] = a.y;
        As[0][ac + 2][ar] = a.z; As[0][ac + 3][ar] = a.w;
        *(float4*)&Bs[0][br][bc] = b;
    }
    __syncthreads();

    const int KT = NFEAT_ / BK;   // 128
    int cur = 0;
    float4 apre, bpre;

    for (int kt = 0; kt < KT; ++kt) {
        if (kt + 1 < KT) {
            const int k0 = (kt + 1) * BK;
            const int gm = m0 + ar;
            apre = make_float4(0.f, 0.f, 0.f, 0.f);
            if (gm < N_NODES) apre = *(const float4*)(X + (size_t)gm * NFEAT_ + k0 + ac);
            bpre = *(const float4*)(W + (size_t)(k0 + br) * DIM + n0 + bc);
        }
#pragma unroll
        for (int kk = 0; kk < BK; ++kk) {
            float4 a0 = *(const float4*)&As[cur][kk][ty * 8];
            float4 a1 = *(const float4*)&As[cur][kk][ty * 8 + 4];
            float4 b0 = *(const float4*)&Bs[cur][kk][tx * 8];
            float4 b1 = *(const float4*)&Bs[cur][kk][tx * 8 + 4];
            float av[8] = {a0.x, a0.y, a0.z, a0.w, a1.x, a1.y, a1.z, a1.w};
            float bv[8] = {b0.x, b0.y, b0.z, b0.w, b1.x, b1.y, b1.z, b1.w};
#pragma unroll
            for (int i = 0; i < 8; ++i)
#pragma unroll
                for (int j = 0; j < 8; ++j)
                    acc[i][j] += av[i] * bv[j];
        }
        if (kt + 1 < KT) {
            const int nxt = cur ^ 1;
            As[nxt][ac + 0][ar] = apre.x; As[nxt][ac + 1][ar] = apre.y;
            As[nxt][ac + 2][ar] = apre.z; As[nxt][ac + 3][ar] = apre.w;
            *(float4*)&Bs[nxt][br][bc] = bpre;
            __syncthreads();
            cur = nxt;
        }
    }

    // epilogue: bias + relu
    const int gn = n0 + tx * 8;
    float bb[8];
#pragma unroll
    for (int j = 0; j < 8; ++j) bb[j] = Bias[gn + j];

#pragma unroll
    for (int i = 0; i < 8; ++i) {
        const int gm = m0 + ty * 8 + i;
        if (gm < N_NODES) {
            float4 o0, o1;
            o0.x = fmaxf(acc[i][0] + bb[0], 0.f);
            o0.y = fmaxf(acc[i][1] + bb[1], 0.f);
            o0.z = fmaxf(acc[i][2] + bb[2], 0.f);
            o0.w = fmaxf(acc[i][3] + bb[3], 0.f);
            o1.x = fmaxf(acc[i][4] + bb[4], 0.f);
            o1.y = fmaxf(acc[i][5] + bb[5], 0.f);
            o1.z = fmaxf(acc[i][6] + bb[6], 0.f);
            o1.w = fmaxf(acc[i][7] + bb[7], 0.f);
            *(float4*)&g_h0[(size_t)gm * DIM + gn]     = o0;
            *(float4*)&g_h0[(size_t)gm * DIM + gn + 4] = o1;
        }
    }
}

// ---------------------------------------------------------------------------
// Kernel 2: layer-0 prep:
//   x_dis = l2norm_percap(h0); x = relu(fc(x_dis)); xa = l2norm_percap(x)
// One block handles 8 nodes; fc_w staged once in padded shared (conflict-free).
// ---------------------------------------------------------------------------
#define NODES_PER_BLK 8

__global__ __launch_bounds__(256)
void prep0_kernel(const float* __restrict__ fcw, const float* __restrict__ fcb)
{
    __shared__ float wsh[KCAPS * DDIM * 33];   // row (k*32+o), stride 33
    __shared__ float xsh[KCAPS * 33];

    const int t = threadIdx.x;
    const int k = t >> 5;
    const int d = t & 31;

    for (int g = t; g < KCAPS * DDIM * DDIM; g += 256)
        wsh[(g >> 5) * 33 + (g & 31)] = fcw[g];
    const float bterm = fcb[t];   // fc_b[k][o], o == d
    __syncthreads();

    for (int s = 0; s < NODES_PER_BLK; ++s) {
        const int n = blockIdx.x * NODES_PER_BLK + s;
        float h = g_h0[(size_t)n * DIM + t];
        float ss = h * h;
#pragma unroll
        for (int off = 16; off; off >>= 1) ss += __shfl_xor_sync(0xffffffffu, ss, off);
        const float xd = h / fmaxf(sqrtf(ss), 1e-12f);
        xsh[k * 33 + d] = xd;
        __syncthreads();

        const float* wr = &wsh[t * 33];       // fc_w row (k*32+o)
        const float* xr = &xsh[k * 33];
        float y = bterm;
#pragma unroll
        for (int i = 0; i < DDIM; ++i) y += xr[i] * wr[i];
        y = fmaxf(y, 0.f);

        float s2 = y * y;
#pragma unroll
        for (int off = 16; off; off >>= 1) s2 += __shfl_xor_sync(0xffffffffu, s2, off);
        g_xa[(size_t)n * DIM + t] = y / fmaxf(sqrtf(s2), 1e-12f);
        __syncthreads();
    }
}

// ---------------------------------------------------------------------------
// Kernel 3: routing layer. One CTA per node, 256 threads.
// Thread t owns capsule k = t>>5 (warp), element d = t&31 (lane).
// z kept in registers (for the u-step) AND in padded shared (for the p-step).
// p1/p2 softmaxes fused into a single weight w = e*(param/s1[k] + q/s2[m]).
// mode 0: write l2norm(relu(u)) to the ping-pong buffer.
// mode 1: write raw u to hout + fused classifier (logits + log_softmax).
// ---------------------------------------------------------------------------
#define ZSTRIDE 36   // float4-aligned, conflict-free

__global__ __launch_bounds__(256)
void routing_kernel(int in_sel, int mode,
                    const int*   __restrict__ nbrs,
                    const float* __restrict__ rawp,
                    const int*   __restrict__ ritp,
                    const float* __restrict__ mlpw,
                    const float* __restrict__ mlpb,
                    float* __restrict__ hout,
                    float* __restrict__ logpout)
{
    __shared__ __align__(16) float z_sh[128 * ZSTRIDE];
    __shared__ __align__(16) float u_sh[KCAPS * ZSTRIDE];
    __shared__ float e_sh[128];
    __shared__ float inv1[KCAPS];
    __shared__ float inv2[M_NB];
    __shared__ int   nb[M_NB];
    __shared__ float logit_sh[NCLS];

    const float* __restrict__ XN = in_sel ? g_xb : g_xa;
    float* __restrict__ OUT = (mode == 1) ? hout : (in_sel ? g_xa : g_xb);

    const int n = blockIdx.x;
    const int t = threadIdx.x;
    const int k = t >> 5;
    const int d = t & 31;

    const float param = 1.f / (1.f + expf(-rawp[0]));
    const float q = 1.f - param;
    const float w0 = param * (1.f / 16.f) + q * (1.f / 8.f);
    const int R = ritp[0];

    if (t < M_NB) nb[t] = nbrs[n * M_NB + t];
    float ub = XN[(size_t)n * DIM + t];   // u_before (normalized input)
    float u  = ub;
    __syncthreads();

    // gather z: 16 neighbor rows, coalesced; registers + shared copy
    float zr[M_NB];
#pragma unroll
    for (int m = 0; m < M_NB; ++m) {
        const int idx = nb[m];
        const float v = XN[(size_t)idx * DIM + t];
        zr[m] = v;
        z_sh[(m * 8 + k) * ZSTRIDE + d] = v;
    }
    __syncthreads();

    for (int it = 0; it < R; ++it) {
        float accm = 0.f;
        if (it == 0) {
            // p = 0 -> p1 = 1/16, p2 = 1/8 exactly
#pragma unroll
            for (int m = 0; m < M_NB; ++m) accm += zr[m];
            accm *= w0;
        } else {
            u_sh[k * ZSTRIDE + d] = u;
            __syncthreads();
            if (t < 128) {
                // thread t computes dot for (m = t>>3, k' = t&7); row index == t
                const float4* zrow = (const float4*)&z_sh[t * ZSTRIDE];
                const float4* urow = (const float4*)&u_sh[(t & 7) * ZSTRIDE];
                float dot = 0.f;
#pragma unroll
                for (int c = 0; c < 8; ++c) {
                    float4 zz = zrow[c], uu = urow[c];
                    dot += zz.x * uu.x + zz.y * uu.y + zz.z * uu.z + zz.w * uu.w;
                }
                e_sh[t] = __expf(dot);   // |p| <= 1, no max-shift needed
            }
            __syncthreads();
            if (t < 8) {                         // s1: sum over neighbors per capsule
                float s = 0.f;
#pragma unroll
                for (int m = 0; m < M_NB; ++m) s += e_sh[m * 8 + t];
                inv1[t] = param / s;
            } else if (t >= 32 && t < 48) {      // s2: sum over capsules per neighbor
                const int m = t - 32;
                float s = 0.f;
#pragma unroll
                for (int kk = 0; kk < KCAPS; ++kk) s += e_sh[m * 8 + kk];
                inv2[m] = q / s;
            }
            __syncthreads();
            const float i1 = inv1[k];
#pragma unroll
            for (int m = 0; m < M_NB; ++m) {
                const float w = e_sh[m * 8 + k] * (i1 + inv2[m]);
                accm += zr[m] * w;
            }
        }

        const float unew = ub + accm;
        ub = unew;                   // u_before keeps the PRE-norm value
        if (it < R - 1) {
            float s = unew * unew;
#pragma unroll
            for (int off = 16; off; off >>= 1) s += __shfl_xor_sync(0xffffffffu, s, off);
            u = unew / fmaxf(sqrtf(s), 1e-12f);
        } else {
            u = unew;
        }
        __syncthreads();   // protect e_sh/u_sh before next iteration
    }

    if (mode == 0) {
        // next layer input: l2norm(relu(u)) per capsule
        const float v = fmaxf(ub, 0.f);
        float s = v * v;
#pragma unroll
        for (int off = 16; off; off >>= 1) s += __shfl_xor_sync(0xffffffffu, s, off);
        OUT[(size_t)n * DIM + t] = v / fmaxf(sqrtf(s), 1e-12f);
    } else {
        // final embedding (raw u) + fused classifier
        OUT[(size_t)n * DIM + t] = ub;
        u_sh[k * ZSTRIDE + d] = ub;
        __syncthreads();
        const int warp = t >> 5, lane = t & 31;
#pragma unroll
        for (int jj = 0; jj < 2; ++jj) {
            const int j = warp * 2 + jj;
            float a = 0.f;
#pragma unroll
            for (int ii = 0; ii < 8; ++ii) {
                const int i = lane + 32 * ii;
                a += mlpw[j * DIM + i] * u_sh[ii * ZSTRIDE + lane];
            }
#pragma unroll
            for (int off = 16; off; off >>= 1) a += __shfl_xor_sync(0xffffffffu, a, off);
            if (lane == 0) logit_sh[j] = a + mlpb[j];
        }
        __syncthreads();
        if (t < NCLS) {
            float mx = -1e30f;
#pragma unroll
            for (int j = 0; j < NCLS; ++j) mx = fmaxf(mx, logit_sh[j]);
            float se = 0.f;
#pragma unroll
            for (int j = 0; j < NCLS; ++j) se += expf(logit_sh[j] - mx);
            logpout[n * NCLS + t] = logit_sh[t] - mx - logf(se);
        }
    }
}

// ---------------------------------------------------------------------------
// Launch
// ---------------------------------------------------------------------------
extern "C" void kernel_launch(void* const* d_in, const int* in_sizes, int n_in,
                              void* d_out, int out_size)
{
    const float* x        = (const float*)d_in[0];
    const int*   nbrs     = (const int*)  d_in[1];
    const float* pca_w    = (const float*)d_in[2];
    const float* pca_b    = (const float*)d_in[3];
    const float* rawp     = (const float*)d_in[4];
    const float* fc_w     = (const float*)d_in[5];
    const float* fc_b     = (const float*)d_in[6];
    const float* mlp_w    = (const float*)d_in[7];
    const float* mlp_b    = (const float*)d_in[8];
    const int*   routit   = (const int*)  d_in[9];

    float* out   = (float*)d_out;
    float* logp  = out;                       // [30000, 16] first
    float* hfin  = out + (size_t)N_NODES * NCLS;  // then [30000, 256]

    // 1) pca projection + relu
    dim3 ggrid((N_NODES + BM - 1) / BM, DIM / BN);
    gemm_pca_kernel<<<ggrid, 256>>>(x, pca_w, pca_b);

    // 2) layer-0 prep (norm -> fc -> relu -> norm) -> g_xa
    prep0_kernel<<<N_NODES / NODES_PER_BLK, 256>>>(fc_w, fc_b);

    // 3) routing layers
    routing_kernel<<<N_NODES, 256>>>(0, 0, nbrs, rawp, routit, mlp_w, mlp_b, nullptr, nullptr); // xa -> xb
    routing_kernel<<<N_NODES, 256>>>(1, 0, nbrs, rawp, routit, mlp_w, mlp_b, nullptr, nullptr); // xb -> xa
    routing_kernel<<<N_NODES, 256>>>(0, 1, nbrs, rawp, routit, mlp_w, mlp_b, hfin, logp);       // xa -> out
}

// round 17
// speedup vs baseline: 1.0008x; 1.0008x over previous
#include <cuda_runtime.h>
#include <cstdint>

#define N_NODES 30000
#define M_NB    16
#define NFEAT_  1024
#define NCLS    16
#define KCAPS   8
#define DDIM    32
#define DIM     256

// Scratch buffers (no allocation allowed -> device globals)
__device__ float g_h0[(size_t)N_NODES * DIM];
__device__ float g_xa[(size_t)N_NODES * DIM];
__device__ float g_xb[(size_t)N_NODES * DIM];

// ---------------------------------------------------------------------------
// Kernel 1: h0 = relu(x @ pca_w + pca_b)   [30000,1024]x[1024,256]
// Classic 128x128x8 double-buffered SGEMM, 256 threads, 8x8 microtile.
// ---------------------------------------------------------------------------
#define BM 128
#define BN 128
#define BK 8

__global__ __launch_bounds__(256, 2)
void gemm_pca_kernel(const float* __restrict__ X,
                     const float* __restrict__ W,
                     const float* __restrict__ Bias)
{
    __shared__ __align__(16) float As[2][BK][BM];
    __shared__ __align__(16) float Bs[2][BK][BN];

    const int t  = threadIdx.x;
    const int m0 = blockIdx.x * BM;
    const int n0 = blockIdx.y * BN;

    // A-tile load mapping: 1 float4 per thread
    const int ar = t >> 1;          // 0..127 (row within tile)
    const int ac = (t & 1) * 4;     // 0 or 4 (col within BK)
    // B-tile load mapping: 1 float4 per thread
    const int br = t >> 5;          // 0..7
    const int bc = (t & 31) * 4;    // 0..124

    const int tx = t & 15;
    const int ty = t >> 4;

    float acc[8][8];
#pragma unroll
    for (int i = 0; i < 8; ++i)
#pragma unroll
        for (int j = 0; j < 8; ++j) acc[i][j] = 0.f;

    // preload tile 0
    {
        const int gm = m0 + ar;
        float4 a = make_float4(0.f, 0.f, 0.f, 0.f);
        if (gm < N_NODES) a = *(const float4*)(X + (size_t)gm * NFEAT_ + ac);
        float4 b = *(const float4*)(W + (size_t)br * DIM + n0 + bc);
        As[0][ac + 0][ar] = a.x; As[0][ac + 1][ar] = a.y;
        As[0][ac + 2][ar] = a.z; As[0][ac + 3][ar] = a.w;
        *(float4*)&Bs[0][br][bc] = b;
    }
    __syncthreads();

    const int KT = NFEAT_ / BK;   // 128
    int cur = 0;
    float4 apre, bpre;

    for (int kt = 0; kt < KT; ++kt) {
        if (kt + 1 < KT) {
            const int k0 = (kt + 1) * BK;
            const int gm = m0 + ar;
            apre = make_float4(0.f, 0.f, 0.f, 0.f);
            if (gm < N_NODES) apre = *(const float4*)(X + (size_t)gm * NFEAT_ + k0 + ac);
            bpre = *(const float4*)(W + (size_t)(k0 + br) * DIM + n0 + bc);
        }
#pragma unroll
        for (int kk = 0; kk < BK; ++kk) {
            float4 a0 = *(const float4*)&As[cur][kk][ty * 8];
            float4 a1 = *(const float4*)&As[cur][kk][ty * 8 + 4];
            float4 b0 = *(const float4*)&Bs[cur][kk][tx * 8];
            float4 b1 = *(const float4*)&Bs[cur][kk][tx * 8 + 4];
            float av[8] = {a0.x, a0.y, a0.z, a0.w, a1.x, a1.y, a1.z, a1.w};
            float bv[8] = {b0.x, b0.y, b0.z, b0.w, b1.x, b1.y, b1.z, b1.w};
#pragma unroll
            for (int i = 0; i < 8; ++i)
#pragma unroll
                for (int j = 0; j < 8; ++j)
                    acc[i][j] += av[i] * bv[j];
        }
        if (kt + 1 < KT) {
            const int nxt = cur ^ 1;
            As[nxt][ac + 0][ar] = apre.x; As[nxt][ac + 1][ar] = apre.y;
            As[nxt][ac + 2][ar] = apre.z; As[nxt][ac + 3][ar] = apre.w;
            *(float4*)&Bs[nxt][br][bc] = bpre;
            __syncthreads();
            cur = nxt;
        }
    }

    // epilogue: bias + relu
    const int gn = n0 + tx * 8;
    float bb[8];
#pragma unroll
    for (int j = 0; j < 8; ++j) bb[j] = Bias[gn + j];

#pragma unroll
    for (int i = 0; i < 8; ++i) {
        const int gm = m0 + ty * 8 + i;
        if (gm < N_NODES) {
            float4 o0, o1;
            o0.x = fmaxf(acc[i][0] + bb[0], 0.f);
            o0.y = fmaxf(acc[i][1] + bb[1], 0.f);
            o0.z = fmaxf(acc[i][2] + bb[2], 0.f);
            o0.w = fmaxf(acc[i][3] + bb[3], 0.f);
            o1.x = fmaxf(acc[i][4] + bb[4], 0.f);
            o1.y = fmaxf(acc[i][5] + bb[5], 0.f);
            o1.z = fmaxf(acc[i][6] + bb[6], 0.f);
            o1.w = fmaxf(acc[i][7] + bb[7], 0.f);
            *(float4*)&g_h0[(size_t)gm * DIM + gn]     = o0;
            *(float4*)&g_h0[(size_t)gm * DIM + gn + 4] = o1;
        }
    }
}

// ---------------------------------------------------------------------------
// Kernel 2: layer-0 prep:
//   x_dis = l2norm_percap(h0); x = relu(fc(x_dis)); xa = l2norm_percap(x)
// One block handles 8 nodes; fc_w staged once in padded shared (conflict-free).
// ---------------------------------------------------------------------------
#define NODES_PER_BLK 8

__global__ __launch_bounds__(256)
void prep0_kernel(const float* __restrict__ fcw, const float* __restrict__ fcb)
{
    __shared__ float wsh[KCAPS * DDIM * 33];   // row (k*32+o), stride 33
    __shared__ float xsh[KCAPS * 33];

    const int t = threadIdx.x;
    const int k = t >> 5;
    const int d = t & 31;

    for (int g = t; g < KCAPS * DDIM * DDIM; g += 256)
        wsh[(g >> 5) * 33 + (g & 31)] = fcw[g];
    const float bterm = fcb[t];   // fc_b[k][o], o == d
    __syncthreads();

    for (int s = 0; s < NODES_PER_BLK; ++s) {
        const int n = blockIdx.x * NODES_PER_BLK + s;
        float h = g_h0[(size_t)n * DIM + t];
        float ss = h * h;
#pragma unroll
        for (int off = 16; off; off >>= 1) ss += __shfl_xor_sync(0xffffffffu, ss, off);
        const float xd = h / fmaxf(sqrtf(ss), 1e-12f);
        xsh[k * 33 + d] = xd;
        __syncthreads();

        const float* wr = &wsh[t * 33];       // fc_w row (k*32+o)
        const float* xr = &xsh[k * 33];
        float y = bterm;
#pragma unroll
        for (int i = 0; i < DDIM; ++i) y += xr[i] * wr[i];
        y = fmaxf(y, 0.f);

        float s2 = y * y;
#pragma unroll
        for (int off = 16; off; off >>= 1) s2 += __shfl_xor_sync(0xffffffffu, s2, off);
        g_xa[(size_t)n * DIM + t] = y / fmaxf(sqrtf(s2), 1e-12f);
        __syncthreads();
    }
}

// ---------------------------------------------------------------------------
// Kernel 3: routing layer. One CTA per node, 256 threads.
// Thread t owns capsule k = t>>5 (warp), element d = t&31 (lane).
// z kept in registers (for the u-step) AND in padded shared (for the p-step).
// p1/p2 softmaxes fused into a single weight w = e*(param/s1[k] + q/s2[m]).
// mode 0: write l2norm(relu(u)) to the ping-pong buffer.
// mode 1: write raw u to hout + fused classifier (logits + log_softmax).
// ---------------------------------------------------------------------------
#define ZSTRIDE 36   // float4-aligned, conflict-free

__global__ __launch_bounds__(256)
void routing_kernel(int in_sel, int mode,
                    const int*   __restrict__ nbrs,
                    const float* __restrict__ rawp,
                    const int*   __restrict__ ritp,
                    const float* __restrict__ mlpw,
                    const float* __restrict__ mlpb,
                    float* __restrict__ hout,
                    float* __restrict__ logpout)
{
    __shared__ __align__(16) float z_sh[128 * ZSTRIDE];
    __shared__ __align__(16) float u_sh[KCAPS * ZSTRIDE];
    __shared__ float e_sh[128];
    __shared__ float inv1[KCAPS];
    __shared__ float inv2[M_NB];
    __shared__ int   nb[M_NB];
    __shared__ float logit_sh[NCLS];

    const float* __restrict__ XN = in_sel ? g_xb : g_xa;
    float* __restrict__ OUT = (mode == 1) ? hout : (in_sel ? g_xa : g_xb);

    const int n = blockIdx.x;
    const int t = threadIdx.x;
    const int k = t >> 5;
    const int d = t & 31;

    const float param = 1.f / (1.f + expf(-rawp[0]));
    const float q = 1.f - param;
    const float w0 = param * (1.f / 16.f) + q * (1.f / 8.f);
    const int R = ritp[0];

    if (t < M_NB) nb[t] = nbrs[n * M_NB + t];
    float ub = XN[(size_t)n * DIM + t];   // u_before (normalized input)
    float u  = ub;
    __syncthreads();

    // gather z: 16 neighbor rows, coalesced; registers + shared copy
    float zr[M_NB];
#pragma unroll
    for (int m = 0; m < M_NB; ++m) {
        const int idx = nb[m];
        const float v = XN[(size_t)idx * DIM + t];
        zr[m] = v;
        z_sh[(m * 8 + k) * ZSTRIDE + d] = v;
    }
    __syncthreads();

    for (int it = 0; it < R; ++it) {
        float accm = 0.f;
        if (it == 0) {
            // p = 0 -> p1 = 1/16, p2 = 1/8 exactly
#pragma unroll
            for (int m = 0; m < M_NB; ++m) accm += zr[m];
            accm *= w0;
        } else {
            u_sh[k * ZSTRIDE + d] = u;
            __syncthreads();
            if (t < 128) {
                // thread t computes dot for (m = t>>3, k' = t&7); row index == t
                const float4* zrow = (const float4*)&z_sh[t * ZSTRIDE];
                const float4* urow = (const float4*)&u_sh[(t & 7) * ZSTRIDE];
                float dot = 0.f;
#pragma unroll
                for (int c = 0; c < 8; ++c) {
                    float4 zz = zrow[c], uu = urow[c];
                    dot += zz.x * uu.x + zz.y * uu.y + zz.z * uu.z + zz.w * uu.w;
                }
                e_sh[t] = __expf(dot);   // |p| <= 1, no max-shift needed
            }
            __syncthreads();
            if (t < 8) {                         // s1: sum over neighbors per capsule
                float s = 0.f;
#pragma unroll
                for (int m = 0; m < M_NB; ++m) s += e_sh[m * 8 + t];
                inv1[t] = param / s;
            } else if (t >= 32 && t < 48) {      // s2: sum over capsules per neighbor
                const int m = t - 32;
                float s = 0.f;
#pragma unroll
                for (int kk = 0; kk < KCAPS; ++kk) s += e_sh[m * 8 + kk];
                inv2[m] = q / s;
            }
            __syncthreads();
            const float i1 = inv1[k];
#pragma unroll
            for (int m = 0; m < M_NB; ++m) {
                const float w = e_sh[m * 8 + k] * (i1 + inv2[m]);
                accm += zr[m] * w;
            }
        }

        const float unew = ub + accm;
        ub = unew;                   // u_before keeps the PRE-norm value
        if (it < R - 1) {
            float s = unew * unew;
#pragma unroll
            for (int off = 16; off; off >>= 1) s += __shfl_xor_sync(0xffffffffu, s, off);
            u = unew / fmaxf(sqrtf(s), 1e-12f);
        } else {
            u = unew;
        }
        __syncthreads();   // protect e_sh/u_sh before next iteration
    }

    if (mode == 0) {
        // next layer input: l2norm(relu(u)) per capsule
        const float v = fmaxf(ub, 0.f);
        float s = v * v;
#pragma unroll
        for (int off = 16; off; off >>= 1) s += __shfl_xor_sync(0xffffffffu, s, off);
        OUT[(size_t)n * DIM + t] = v / fmaxf(sqrtf(s), 1e-12f);
    } else {
        // final embedding (raw u) + fused classifier
        OUT[(size_t)n * DIM + t] = ub;
        u_sh[k * ZSTRIDE + d] = ub;
        __syncthreads();
        const int warp = t >> 5, lane = t & 31;
#pragma unroll
        for (int jj = 0; jj < 2; ++jj) {
            const int j = warp * 2 + jj;
            float a = 0.f;
#pragma unroll
            for (int ii = 0; ii < 8; ++ii) {
                const int i = lane + 32 * ii;
                a += mlpw[j * DIM + i] * u_sh[ii * ZSTRIDE + lane];
            }
#pragma unroll
            for (int off = 16; off; off >>= 1) a += __shfl_xor_sync(0xffffffffu, a, off);
            if (lane == 0) logit_sh[j] = a + mlpb[j];
        }
        __syncthreads();
        if (t < NCLS) {
            float mx = -1e30f;
#pragma unroll
            for (int j = 0; j < NCLS; ++j) mx = fmaxf(mx, logit_sh[j]);
            float se = 0.f;
#pragma unroll
            for (int j = 0; j < NCLS; ++j) se += expf(logit_sh[j] - mx);
            logpout[n * NCLS + t] = logit_sh[t] - mx - logf(se);
        }
    }
}

// ---------------------------------------------------------------------------
// Launch
// ---------------------------------------------------------------------------
extern "C" void kernel_launch(void* const* d_in, const int* in_sizes, int n_in,
                              void* d_out, int out_size)
{
    const float* x        = (const float*)d_in[0];
    const int*   nbrs     = (const int*)  d_in[1];
    const float* pca_w    = (const float*)d_in[2];
    const float* pca_b    = (const float*)d_in[3];
    const float* rawp     = (const float*)d_in[4];
    const float* fc_w     = (const float*)d_in[5];
    const float* fc_b     = (const float*)d_in[6];
    const float* mlp_w    = (const float*)d_in[7];
    const float* mlp_b    = (const float*)d_in[8];
    const int*   routit   = (const int*)  d_in[9];

    float* out   = (float*)d_out;
    float* logp  = out;                       // [30000, 16] first
    float* hfin  = out + (size_t)N_NODES * NCLS;  // then [30000, 256]

    // 1) pca projection + relu
    dim3 ggrid((N_NODES + BM - 1) / BM, DIM / BN);
    gemm_pca_kernel<<<ggrid, 256>>>(x, pca_w, pca_b);

    // 2) layer-0 prep (norm -> fc -> relu -> norm) -> g_xa
    prep0_kernel<<<N_NODES / NODES_PER_BLK, 256>>>(fc_w, fc_b);

    // 3) routing layers
    routing_kernel<<<N_NODES, 256>>>(0, 0, nbrs, rawp, routit, mlp_w, mlp_b, nullptr, nullptr); // xa -> xb
    routing_kernel<<<N_NODES, 256>>>(1, 0, nbrs, rawp, routit, mlp_w, mlp_b, nullptr, nullptr); // xb -> xa
    routing_kernel<<<N_NODES, 256>>>(0, 1, nbrs, rawp, routit, mlp_w, mlp_b, hfin, logp);       // xa -> out
}